// round 7
// baseline (speedup 1.0000x reference)
#include <cuda_runtime.h>
#include <cuda_bf16.h>
#include <stdint.h>

// RandomShiftsAug == integer shift + replicate-pad gather:
//   out[n,c,i,j] = x[n,c, clamp(i+sy-4,0,223), clamp(j+sx-4,0,223)]
// (grid coords are exactly integer; bilinear weights degenerate to {1,0}).
//
// R5/R6: 2 rows per thread -> 14 front-batched independent LDG.32 per thread
// (MLP 14 vs 7) to raise DRAM occupancy from 79% toward the HBM wall.
// Warp-stride-32 mapping kept: each LDG across a warp = 128 contiguous bytes,
// each STG across a warp = exactly one aligned 128B line (pitch 896B = 7*128B).

#define H 224
#define W 224
#define C 9
#define PAD 4
#define RY 8      // blockDim.y
#define RPB 16    // rows per block (2 per thread)

__global__ __launch_bounds__(256) void random_shift_kernel(
    const float* __restrict__ x,
    const int*   __restrict__ shift,
    float*       __restrict__ out)
{
    const int nc = blockIdx.y;                    // 0 .. n*C-1
    const int n  = nc / C;
    const int i0 = blockIdx.x * RPB + threadIdx.y;   // first output row
    const int i1 = i0 + RY;                          // second output row
    const int tx = threadIdx.x;                   // 0..31 column phase

    const int dx = __ldg(shift + 2 * n + 0) - PAD;   // [-4, 4]
    const int dy = __ldg(shift + 2 * n + 1) - PAD;   // [-4, 4]

    const int s0 = min(max(i0 + dy, 0), H - 1);
    const int s1 = min(max(i1 + dy, 0), H - 1);

    const float* __restrict__ src0 = x + ((size_t)nc * H + s0) * W;
    const float* __restrict__ src1 = x + ((size_t)nc * H + s1) * W;
    float* __restrict__ dst0 = out + ((size_t)nc * H + i0) * W;
    float* __restrict__ dst1 = out + ((size_t)nc * H + i1) * W;

    // 224 = 7 * 32 columns per row; thread tx owns columns tx + 32*c.
    float v0[7], v1[7];
    #pragma unroll
    for (int c = 0; c < 7; c++) {
        const int jc = min(max(tx + 32 * c + dx, 0), W - 1);
        v0[c] = __ldg(src0 + jc);
        v1[c] = __ldg(src1 + jc);
    }
    #pragma unroll
    for (int c = 0; c < 7; c++) {
        dst0[tx + 32 * c] = v0[c];
        dst1[tx + 32 * c] = v1[c];
    }
}

extern "C" void kernel_launch(void* const* d_in, const int* in_sizes, int n_in,
                              void* d_out, int out_size)
{
    const float* x     = (const float*)d_in[0];   // (128, 9, 224, 224) fp32
    const int*   shift = (const int*)d_in[1];     // (128, 1, 1, 2) int32
    float* out = (float*)d_out;

    const int n = in_sizes[1] / 2;                // 128 batches

    dim3 block(32, RY, 1);                        // 256 threads
    dim3 grid(H / RPB, n * C, 1);                 // (14, 1152)
    random_shift_kernel<<<grid, block>>>(x, shift, out);
}

// round 8
// speedup vs baseline: 1.0333x; 1.0333x over previous
#include <cuda_runtime.h>
#include <cuda_bf16.h>
#include <stdint.h>

// RandomShiftsAug == integer shift + replicate-pad gather:
//   out[n,c,i,j] = x[n,c, clamp(i+sy-4,0,223), clamp(j+sx-4,0,223)]
// (grid coords are exactly integer; bilinear weights degenerate to {1,0}).
//
// R7: measured evidence (two kernels pegged at 6.26-6.28 TB/s) says we are at
// the B300 LTS chip cap (~6300 B/cyc, path-independent) with compulsory-only
// traffic -> ncu time is at the floor (~65us). Revert to the best wall-time
// mapping (R4: 1 row/thread, warp-stride-32) and add streaming cache hints
// (__ldcs/__stcs) to minimize L2 interference between read and write streams.

#define H 224
#define W 224
#define C 9
#define PAD 4
#define ROWS 8   // rows per block (blockDim.y)

__global__ __launch_bounds__(256) void random_shift_kernel(
    const float* __restrict__ x,
    const int*   __restrict__ shift,
    float*       __restrict__ out)
{
    const int nc = blockIdx.y;                    // 0 .. n*C-1
    const int n  = nc / C;
    const int i  = blockIdx.x * ROWS + threadIdx.y;   // output row
    const int tx = threadIdx.x;                   // 0..31, column phase

    const int dx = __ldg(shift + 2 * n + 0) - PAD;    // [-4, 4]
    const int dy = __ldg(shift + 2 * n + 1) - PAD;    // [-4, 4]

    const int si = min(max(i + dy, 0), H - 1);
    const float* __restrict__ src = x   + ((size_t)nc * H + si) * W;
    float*       __restrict__ dst = out + ((size_t)nc * H + i) * W;

    // 224 = 7 * 32 columns per row; thread tx owns columns tx + 32*c.
    // Each warp LDG = 128 contiguous bytes (<=2 lines with dx misalignment);
    // each warp STG = exactly one aligned 128B line (row pitch 896B = 7*128B).
    float v[7];
    #pragma unroll
    for (int c = 0; c < 7; c++) {
        const int j = tx + 32 * c;
        v[c] = __ldcs(src + min(max(j + dx, 0), W - 1));
    }
    #pragma unroll
    for (int c = 0; c < 7; c++) {
        __stcs(dst + tx + 32 * c, v[c]);
    }
}

extern "C" void kernel_launch(void* const* d_in, const int* in_sizes, int n_in,
                              void* d_out, int out_size)
{
    const float* x     = (const float*)d_in[0];   // (128, 9, 224, 224) fp32
    const int*   shift = (const int*)d_in[1];     // (128, 1, 1, 2) int32
    float* out = (float*)d_out;

    const int n = in_sizes[1] / 2;                // 128 batches

    dim3 block(32, ROWS, 1);                      // 256 threads
    dim3 grid(H / ROWS, n * C, 1);                // (28, 1152)
    random_shift_kernel<<<grid, block>>>(x, shift, out);
}